// round 2
// baseline (speedup 1.0000x reference)
#include <cuda_runtime.h>

// PairwiseScore: out[b,i,j] = (m_i + m_j + MLP3(g_i, g_j)) / 3
// B=2, N=256, E=512, H=150.
// Structure: one CTA per (b,i). For fixed i, layer1 is a 256x512x150 GEMM
// of (G_b * g_i) @ W1c, fused with +HI_i +HJ_j, relu, then 256x150x150 GEMM
// with W2, relu, then dot with w3.

namespace {
constexpr int B_ = 2, N_ = 256, E_ = 512, H_ = 150;
}

// Scratch (no cudaMalloc allowed): HI = g@W1a + b1, HJ = g@W1b
__device__ float g_HI[B_ * N_ * H_];
__device__ float g_HJ[B_ * N_ * H_];

// ---------------------------------------------------------------------------
// Kernel 1: precompute HI/HJ.  64 blocks x 256 threads, 8 rows per block.
// Thread map: tx = tid&31 handles h = tx + 32k (k<5), ty = tid>>5 is the row.
// ---------------------------------------------------------------------------
__global__ void __launch_bounds__(256) k_precompute(
    const float* __restrict__ g, const float* __restrict__ W1,
    const float* __restrict__ b1)
{
    // [8][33] g rows | [32][152] W1a tile | [32][152] W1b tile | pad
    __shared__ float sm[8 * 33 + 2 * 32 * 152 + 64];
    float* gs = sm;
    float* wa = sm + 8 * 33;
    float* wb = wa + 32 * 152;

    const int tid = threadIdx.x;
    const int tx = tid & 31;
    const int ty = tid >> 5;          // 0..7
    const int r0 = blockIdx.x * 8;    // global row = b*N + n

    float acca[5] = {0.f, 0.f, 0.f, 0.f, 0.f};
    float accb[5] = {0.f, 0.f, 0.f, 0.f, 0.f};

    for (int ec = 0; ec < E_; ec += 32) {
        __syncthreads();
        {   // 8x32 = 256 elements, one per thread
            int jj = tid >> 5, ee = tid & 31;
            gs[jj * 33 + ee] = g[(r0 + jj) * E_ + ec + ee];
        }
        for (int q = tid; q < 32 * H_; q += 256) {
            int r = q / H_, c = q % H_;
            wa[r * 152 + c] = W1[(ec + r) * H_ + c];
            wb[r * 152 + c] = W1[(E_ + ec + r) * H_ + c];
        }
        __syncthreads();
#pragma unroll 8
        for (int e = 0; e < 32; e++) {
            float a = gs[ty * 33 + e];
#pragma unroll
            for (int k = 0; k < 5; k++) {
                acca[k] += a * wa[e * 152 + tx + 32 * k];
                accb[k] += a * wb[e * 152 + tx + 32 * k];
            }
        }
    }

    const int row = r0 + ty;
#pragma unroll
    for (int k = 0; k < 5; k++) {
        int h = tx + 32 * k;
        if (h < H_) {
            g_HI[row * H_ + h] = acca[k] + b1[h];
            g_HJ[row * H_ + h] = accb[k];
        }
    }
}

// ---------------------------------------------------------------------------
// Kernel 2: main fused pairwise MLP. Grid = B*N (one CTA per (b,i)),
// 128 threads. tx = tid&15 (h-group: h = tx+16k, k<10), ty = tid>>4 (0..7),
// per-thread tile 8j x 10h, j-tile of 64 (j = jb + ty + 8l).
// ---------------------------------------------------------------------------
// smem layout (float offsets):
constexpr int SM_GI  = 0;                    // 512  : g[b,i,:]
constexpr int SM_HII = 512;                  // 152  : HI[b,i,:] (incl b1)
constexpr int SM_W3  = 664;                  // 152  : W3
constexpr int SM_B2  = 816;                  // 152  : b2
constexpr int SM_GS  = 968;                  // 64*33  = 2112 : scaled-g tile
constexpr int SM_WS  = SM_GS + 64 * 33;      // 32*152 = 4864 : W tile (W1c/W2)
constexpr int SM_H1  = SM_WS + 32 * 152;     // 64*153 = 9792 : layer1 output
constexpr int SM_TOT = SM_H1 + 64 * 153;     // 17736 floats = 70944 bytes

__global__ void __launch_bounds__(128) k_pairwise(
    const float* __restrict__ g, const float* __restrict__ ment,
    const float* __restrict__ W1, const float* __restrict__ W2,
    const float* __restrict__ b2, const float* __restrict__ W3,
    const float* __restrict__ b3, float* __restrict__ out)
{
    extern __shared__ float sm[];
    const int tid = threadIdx.x;
    const int tx = tid & 15;   // 0..15
    const int ty = tid >> 4;   // 0..7
    const int b = blockIdx.x >> 8;
    const int i = blockIdx.x & (N_ - 1);
    const int rowi = b * N_ + i;

    for (int q = tid; q < E_; q += 128) sm[SM_GI + q] = g[rowi * E_ + q];
    for (int q = tid; q < H_; q += 128) {
        sm[SM_HII + q] = g_HI[rowi * H_ + q];
        sm[SM_W3 + q]  = W3[q];
        sm[SM_B2 + q]  = b2[q];
    }
    __syncthreads();

    const float mi  = ment[rowi];
    const float b3v = b3[0];

    for (int jb = 0; jb < N_; jb += 64) {
        // ---------------- layer 1: acc = (g_j * g_i) @ W1c ----------------
        float acc[8][10];
#pragma unroll
        for (int l = 0; l < 8; l++)
#pragma unroll
            for (int k = 0; k < 10; k++) acc[l][k] = 0.f;

        for (int ec = 0; ec < E_; ec += 32) {
            __syncthreads();
            for (int q = tid; q < 64 * 32; q += 128) {
                int jj = q >> 5, ee = q & 31;
                sm[SM_GS + jj * 33 + ee] =
                    g[(b * N_ + jb + jj) * E_ + ec + ee] * sm[SM_GI + ec + ee];
            }
            for (int q = tid; q < 32 * H_; q += 128) {
                int r = q / H_, c = q % H_;
                sm[SM_WS + r * 152 + c] = W1[(2 * E_ + ec + r) * H_ + c];
            }
            __syncthreads();
#pragma unroll 4
            for (int e = 0; e < 32; e++) {
                float a[8], w[10];
#pragma unroll
                for (int l = 0; l < 8; l++) a[l] = sm[SM_GS + (ty + 8 * l) * 33 + e];
#pragma unroll
                for (int k = 0; k < 10; k++) w[k] = sm[SM_WS + e * 152 + tx + 16 * k];
#pragma unroll
                for (int l = 0; l < 8; l++)
#pragma unroll
                    for (int k = 0; k < 10; k++) acc[l][k] += a[l] * w[k];
            }
        }

        // epilogue: h1 = relu(acc + HI_i + HJ_j) -> smem
#pragma unroll
        for (int l = 0; l < 8; l++) {
            const int j = jb + ty + 8 * l;
            const float* hjrow = &g_HJ[(b * N_ + j) * H_];
#pragma unroll
            for (int k = 0; k < 10; k++) {
                const int h = tx + 16 * k;
                if (h < H_) {
                    float v = acc[l][k] + sm[SM_HII + h] + hjrow[h];
                    sm[SM_H1 + (ty + 8 * l) * 153 + h] = fmaxf(v, 0.f);
                }
            }
        }
        __syncthreads();

        // ---------------- layer 2: acc2 = h1 @ W2 ----------------
        float acc2[8][10];
#pragma unroll
        for (int l = 0; l < 8; l++)
#pragma unroll
            for (int k = 0; k < 10; k++) acc2[l][k] = 0.f;

        for (int pc = 0; pc < H_; pc += 32) {
            const int pn = (H_ - pc < 32) ? (H_ - pc) : 32;
            for (int q = tid; q < pn * H_; q += 128) {
                int r = q / H_, c = q % H_;
                sm[SM_WS + r * 152 + c] = W2[(pc + r) * H_ + c];
            }
            __syncthreads();
#pragma unroll 4
            for (int p = 0; p < pn; p++) {
                float a[8], w[10];
#pragma unroll
                for (int l = 0; l < 8; l++)
                    a[l] = sm[SM_H1 + (ty + 8 * l) * 153 + pc + p];
#pragma unroll
                for (int k = 0; k < 10; k++) w[k] = sm[SM_WS + p * 152 + tx + 16 * k];
#pragma unroll
                for (int l = 0; l < 8; l++)
#pragma unroll
                    for (int k = 0; k < 10; k++) acc2[l][k] += a[l] * w[k];
            }
            __syncthreads();
        }

        // ---------------- layer 3 + output ----------------
        float part[8];
#pragma unroll
        for (int l = 0; l < 8; l++) {
            float s = 0.f;
#pragma unroll
            for (int k = 0; k < 10; k++) {
                const int h = tx + 16 * k;
                if (h < H_) {
                    float y2 = fmaxf(acc2[l][k] + sm[SM_B2 + h], 0.f);
                    s += y2 * sm[SM_W3 + h];
                }
            }
            // reduce across the 16 tx lanes (stays within half-warp)
            s += __shfl_xor_sync(0xffffffffu, s, 8);
            s += __shfl_xor_sync(0xffffffffu, s, 4);
            s += __shfl_xor_sync(0xffffffffu, s, 2);
            s += __shfl_xor_sync(0xffffffffu, s, 1);
            part[l] = s;
        }
        if (tx == 0) {
#pragma unroll
            for (int l = 0; l < 8; l++) {
                const int j = jb + ty + 8 * l;
                const float ps = part[l] + b3v;
                out[rowi * N_ + j] = (mi + ment[b * N_ + j] + ps) * (1.0f / 3.0f);
            }
        }
        __syncthreads();
    }
}

// ---------------------------------------------------------------------------
extern "C" void kernel_launch(void* const* d_in, const int* in_sizes, int n_in,
                              void* d_out, int out_size)
{
    const float* g   = (const float*)d_in[0];
    const float* m   = (const float*)d_in[1];
    const float* W1  = (const float*)d_in[2];
    const float* b1  = (const float*)d_in[3];
    const float* W2  = (const float*)d_in[4];
    const float* b2  = (const float*)d_in[5];
    const float* W3  = (const float*)d_in[6];
    const float* b3  = (const float*)d_in[7];
    float* out = (float*)d_out;

    // >48KB dynamic smem. The first (non-capture) correctness call sets the
    // attribute persistently; ignore the return value on later calls.
    (void)cudaFuncSetAttribute(k_pairwise,
                               cudaFuncAttributeMaxDynamicSharedMemorySize,
                               SM_TOT * (int)sizeof(float));

    k_precompute<<<64, 256>>>(g, W1, b1);
    k_pairwise<<<B_ * N_, 128, SM_TOT * (int)sizeof(float)>>>(
        g, m, W1, W2, b2, W3, b3, out);
}

// round 6
// speedup vs baseline: 5.0758x; 5.0758x over previous
#include <cuda_runtime.h>
#include <cuda_bf16.h>
#include <cstdint>

// PairwiseScore via warp-level bf16 mma.sync (HMMA tensor pipe).
// out[b,i,j] = (m_i + m_j + MLP3(g_i,g_j))/3,  B=2,N=256,E=512,H=150 (pad 160).
// Per CTA (b,i), j-tiles of 64:
//   GEMM1: C1[64,160] = bf16(g_j * g_i)[64,512] @ W1c[512,160]  (8 k-chunks of 64)
//   epi1 : A2 = bf16(relu(C1 + HI_i + HJ_j))
//   GEMM2: C2[64,160] = A2[64,192] @ W2^T[160,192]              (3 k-chunks)
//   epi2 : out = (m_i + m_j + relu(C2+b2).w3 + b3)/3

namespace {
constexpr int B_ = 2, N_ = 256, E_ = 512, H_ = 150;
constexpr int HS = 160;   // padded H
}

// ---- device scratch (no cudaMalloc allowed) ----
__device__ float g_HI[B_ * N_ * HS];
__device__ float g_HJ[B_ * N_ * HS];
// W1c^T bf16 pre-swizzled: 8 chunks x [160 n][64 k]  (20480 B each)
__device__ __align__(16) unsigned char g_W1cT[8 * 20480];
// W2^T bf16 pre-swizzled: 3 chunks x [160 n][64 k]
__device__ __align__(16) unsigned char g_W2T[3 * 20480];

// swizzled byte offset inside a [rows][64] bf16 tile (128 B rows, 8x16B segs)
__device__ __forceinline__ int swz(int row, int k) {
    return row * 128 + (((k >> 3) ^ (row & 7)) * 16) + (k & 7) * 2;
}

__device__ __forceinline__ uint32_t smem_u32(const void* p) {
    uint32_t a;
    asm("{ .reg .u64 t; cvta.to.shared.u64 t, %1; cvt.u32.u64 %0, t; }" : "=r"(a) : "l"(p));
    return a;
}
#define CVT_BF2(res, lo, hi) asm("cvt.rn.bf16x2.f32 %0, %1, %2;" : "=r"(res) : "f"(hi), "f"(lo))

__device__ __forceinline__ void mma16816(float* d, const uint32_t* a, const uint32_t* bf) {
    asm volatile("mma.sync.aligned.m16n8k16.row.col.f32.bf16.bf16.f32 "
                 "{%0,%1,%2,%3}, {%4,%5,%6,%7}, {%8,%9}, {%0,%1,%2,%3};"
                 : "+f"(d[0]), "+f"(d[1]), "+f"(d[2]), "+f"(d[3])
                 : "r"(a[0]), "r"(a[1]), "r"(a[2]), "r"(a[3]), "r"(bf[0]), "r"(bf[1]));
}

// One 64-wide k-chunk: A tile [64][64] at aBase, B tile [160][64] at bBase.
// Warp w computes rows 0..63 x cols w*40..w*40+39 into acc[4 mt][5 nt][4].
__device__ __forceinline__ void gemm_chunk(uint32_t aBase, uint32_t bBase,
                                           int w, int lane, float (*acc)[5][4]) {
#pragma unroll
    for (int ks = 0; ks < 4; ks++) {
        uint32_t a[4][4];
#pragma unroll
        for (int mt = 0; mt < 4; mt++) {
            int row = mt * 16 + ((lane >> 3) & 1) * 8 + (lane & 7);
            int seg = ks * 2 + (lane >> 4);
            uint32_t ad = aBase + row * 128 + ((seg ^ (row & 7)) * 16);
            asm volatile("ldmatrix.sync.aligned.m8n8.x4.shared.b16 {%0,%1,%2,%3}, [%4];"
                         : "=r"(a[mt][0]), "=r"(a[mt][1]), "=r"(a[mt][2]), "=r"(a[mt][3])
                         : "r"(ad));
        }
#pragma unroll
        for (int nt = 0; nt < 5; nt++) {
            int nrow = w * 40 + nt * 8 + (lane & 7);
            int seg = ks * 2 + ((lane >> 3) & 1);
            uint32_t bd = bBase + nrow * 128 + ((seg ^ (nrow & 7)) * 16);
            uint32_t bf[2];
            asm volatile("ldmatrix.sync.aligned.m8n8.x2.shared.b16 {%0,%1}, [%2];"
                         : "=r"(bf[0]), "=r"(bf[1]) : "r"(bd));
#pragma unroll
            for (int mt = 0; mt < 4; mt++) mma16816(acc[mt][nt], a[mt], bf);
        }
    }
}

// smem byte map
constexpr int SM_GI  = 0;        // 512 f  (2048 B)
constexpr int SM_HI  = 2048;     // 160 f
constexpr int SM_W3  = 2688;     // 160 f
constexpr int SM_B2  = 3328;     // 160 f
constexpr int SM_RED = 3968;     // 64*4 f (1024 B)
constexpr int SM_A1  = 4992;     // [64][64] bf16 swz   (8192 B)
constexpr int SM_B   = 13184;    // [160][64] bf16 swz  (20480 B)
constexpr int SM_A2  = 33664;    // 3 x [64][64] bf16   (24576 B)
constexpr int SMEM_BYTES = 58240;

// ---------------------------------------------------------------------------
// Prep kernels
// ---------------------------------------------------------------------------
__global__ void __launch_bounds__(256) k_precompute(
    const float* __restrict__ g, const float* __restrict__ W1,
    const float* __restrict__ b1)
{
    __shared__ float sm[8 * 33 + 2 * 32 * 152 + 64];
    float* gs = sm;
    float* wa = sm + 8 * 33;
    float* wb = wa + 32 * 152;
    const int tid = threadIdx.x, tx = tid & 31, ty = tid >> 5;
    const int r0 = blockIdx.x * 8;
    float acca[5] = {0, 0, 0, 0, 0}, accb[5] = {0, 0, 0, 0, 0};
    for (int ec = 0; ec < E_; ec += 32) {
        __syncthreads();
        { int jj = tid >> 5, ee = tid & 31; gs[jj * 33 + ee] = g[(r0 + jj) * E_ + ec + ee]; }
        for (int q = tid; q < 32 * H_; q += 256) {
            int r = q / H_, c = q % H_;
            wa[r * 152 + c] = W1[(ec + r) * H_ + c];
            wb[r * 152 + c] = W1[(E_ + ec + r) * H_ + c];
        }
        __syncthreads();
#pragma unroll 8
        for (int e = 0; e < 32; e++) {
            float a = gs[ty * 33 + e];
#pragma unroll
            for (int k = 0; k < 5; k++) {
                acca[k] += a * wa[e * 152 + tx + 32 * k];
                accb[k] += a * wb[e * 152 + tx + 32 * k];
            }
        }
    }
    const int row = r0 + ty;
#pragma unroll
    for (int k = 0; k < 5; k++) {
        int h = tx + 32 * k;   // 0..159
        bool v = (h < H_);
        g_HI[row * HS + h] = v ? (acca[k] + b1[h]) : 0.f;
        g_HJ[row * HS + h] = v ? accb[k] : 0.f;
    }
}

__global__ void __launch_bounds__(256) k_prep_w1c(const float* __restrict__ W1) {
    int idx = blockIdx.x * 256 + threadIdx.x;
    if (idx >= 8 * 160 * 64) return;
    int c = idx / (160 * 64), r = idx % (160 * 64);
    int n = r / 64, k = r % 64;
    float v = (n < H_) ? W1[(2 * E_ + c * 64 + k) * H_ + n] : 0.f;
    *(__nv_bfloat16*)(g_W1cT + c * 20480 + swz(n, k)) = __float2bfloat16(v);
}
__global__ void __launch_bounds__(256) k_prep_w2t(const float* __restrict__ W2) {
    int idx = blockIdx.x * 256 + threadIdx.x;
    if (idx >= 3 * 160 * 64) return;
    int c = idx / (160 * 64), r = idx % (160 * 64);
    int n = r / 64, k = r % 64;
    int kk = c * 64 + k;
    float v = (n < H_ && kk < H_) ? W2[kk * H_ + n] : 0.f;
    *(__nv_bfloat16*)(g_W2T + c * 20480 + swz(n, k)) = __float2bfloat16(v);
}

// ---------------------------------------------------------------------------
// Main kernel: one CTA per (b,i), 128 threads (4 warps)
// ---------------------------------------------------------------------------
__global__ void __launch_bounds__(128) k_main(
    const float* __restrict__ g, const float* __restrict__ ment,
    const float* __restrict__ b2, const float* __restrict__ W3,
    const float* __restrict__ b3, float* __restrict__ out)
{
    extern __shared__ char smc[];
    float* smf = (float*)smc;
    const uint32_t sb = smem_u32(smc);
    const int tid = threadIdx.x, w = tid >> 5, lane = tid & 31;
    const int b = blockIdx.x >> 8;
    const int rowi = blockIdx.x;

    for (int q = tid; q < E_; q += 128) smf[SM_GI / 4 + q] = g[rowi * E_ + q];
    for (int q = tid; q < HS; q += 128) {
        bool v = (q < H_);
        smf[SM_HI / 4 + q] = v ? g_HI[rowi * HS + q] : 0.f;
        smf[SM_W3 / 4 + q] = v ? W3[q] : 0.f;
        smf[SM_B2 / 4 + q] = v ? b2[q] : 0.f;
    }
    {   // zero sA2 chunk 2 (its k=160..191 half stays zero forever)
        uint4 z = make_uint4(0, 0, 0, 0);
        for (int q = tid; q < 512; q += 128)
            ((uint4*)(smc + SM_A2 + 2 * 8192))[q] = z;
    }

    const float mi = ment[rowi];
    const float b3v = b3[0];

    for (int jt = 0; jt < 4; jt++) {
        const int jb = jt * 64;
        // ================= GEMM1 =================
        float c1[4][5][4];
#pragma unroll
        for (int mt = 0; mt < 4; mt++)
#pragma unroll
            for (int nt = 0; nt < 5; nt++)
#pragma unroll
                for (int q = 0; q < 4; q++) c1[mt][nt][q] = 0.f;

        for (int c = 0; c < 8; c++) {
            __syncthreads();
            {   // B chunk: linear pre-swizzled copy (1280 uint4)
                const uint4* src = (const uint4*)(g_W1cT + c * 20480);
                uint4* dst = (uint4*)(smc + SM_B);
                for (int q = tid; q < 1280; q += 128) dst[q] = src[q];
            }
#pragma unroll
            for (int s4 = 0; s4 < 4; s4++) {   // A fill: 4 x 16B segs per thread
                int s = s4 * 128 + tid;        // 0..511
                int row = s >> 3, seg = s & 7;
                const float4* gp = (const float4*)(g + (b * N_ + jb + row) * E_ + c * 64 + seg * 8);
                float4 ga = gp[0], gb = gp[1];
                const float4* ip = (const float4*)(smf + SM_GI / 4 + c * 64 + seg * 8);
                float4 ia = ip[0], ib = ip[1];
                uint32_t p0, p1, p2, p3;
                CVT_BF2(p0, ga.x * ia.x, ga.y * ia.y);
                CVT_BF2(p1, ga.z * ia.z, ga.w * ia.w);
                CVT_BF2(p2, gb.x * ib.x, gb.y * ib.y);
                CVT_BF2(p3, gb.z * ib.z, gb.w * ib.w);
                *(uint4*)(smc + SM_A1 + row * 128 + ((seg ^ (row & 7)) * 16)) =
                    make_uint4(p0, p1, p2, p3);
            }
            __syncthreads();
            gemm_chunk(sb + SM_A1, sb + SM_B, w, lane, c1);
        }

        // ================= epilogue 1 -> A2 (bf16, swizzled chunks) ==========
        {
            const float* hjb = g_HJ + (b * N_ + jb) * HS;
#pragma unroll
            for (int mt = 0; mt < 4; mt++) {
                int r0 = mt * 16 + (lane >> 2);
#pragma unroll
                for (int nt = 0; nt < 5; nt++) {
                    int h = w * 40 + nt * 8 + (lane & 3) * 2;
                    float2 hi2 = *(const float2*)(smf + SM_HI / 4 + h);
                    float2 hj0 = *(const float2*)(hjb + r0 * HS + h);
                    float2 hj8 = *(const float2*)(hjb + (r0 + 8) * HS + h);
                    float v0 = fmaxf(c1[mt][nt][0] + hi2.x + hj0.x, 0.f);
                    float v1 = fmaxf(c1[mt][nt][1] + hi2.y + hj0.y, 0.f);
                    float v2 = fmaxf(c1[mt][nt][2] + hi2.x + hj8.x, 0.f);
                    float v3 = fmaxf(c1[mt][nt][3] + hi2.y + hj8.y, 0.f);
                    uint32_t pk;
                    int base = SM_A2 + (h >> 6) * 8192;
                    int kk = h & 63;
                    CVT_BF2(pk, v0, v1);
                    *(uint32_t*)(smc + base + swz(r0, kk)) = pk;
                    CVT_BF2(pk, v2, v3);
                    *(uint32_t*)(smc + base + swz(r0 + 8, kk)) = pk;
                }
            }
        }

        // ================= GEMM2 =================
        float c2[4][5][4];
#pragma unroll
        for (int mt = 0; mt < 4; mt++)
#pragma unroll
            for (int nt = 0; nt < 5; nt++)
#pragma unroll
                for (int q = 0; q < 4; q++) c2[mt][nt][q] = 0.f;

        for (int c = 0; c < 3; c++) {
            __syncthreads();
            {
                const uint4* src = (const uint4*)(g_W2T + c * 20480);
                uint4* dst = (uint4*)(smc + SM_B);
                for (int q = tid; q < 1280; q += 128) dst[q] = src[q];
            }
            __syncthreads();
            gemm_chunk(sb + SM_A2 + c * 8192, sb + SM_B, w, lane, c2);
        }

        // ================= epilogue 2 -> output =================
        {
            float rs0[4], rs8[4];
#pragma unroll
            for (int mt = 0; mt < 4; mt++) {
                float s0 = 0.f, s8 = 0.f;
#pragma unroll
                for (int nt = 0; nt < 5; nt++) {
                    int h = w * 40 + nt * 8 + (lane & 3) * 2;
                    float w30 = smf[SM_W3 / 4 + h], w31 = smf[SM_W3 / 4 + h + 1];
                    float bb0 = smf[SM_B2 / 4 + h], bb1 = smf[SM_B2 / 4 + h + 1];
                    s0 += fmaxf(c2[mt][nt][0] + bb0, 0.f) * w30
                        + fmaxf(c2[mt][nt][1] + bb1, 0.f) * w31;
                    s8 += fmaxf(c2[mt][nt][2] + bb0, 0.f) * w30
                        + fmaxf(c2[mt][nt][3] + bb1, 0.f) * w31;
                }
                s0 += __shfl_xor_sync(0xffffffffu, s0, 1);
                s0 += __shfl_xor_sync(0xffffffffu, s0, 2);
                s8 += __shfl_xor_sync(0xffffffffu, s8, 1);
                s8 += __shfl_xor_sync(0xffffffffu, s8, 2);
                rs0[mt] = s0; rs8[mt] = s8;
            }
            if ((lane & 3) == 0) {
                int rr = lane >> 2;
#pragma unroll
                for (int mt = 0; mt < 4; mt++) {
                    smf[SM_RED / 4 + (mt * 16 + rr) * 4 + w] = rs0[mt];
                    smf[SM_RED / 4 + (mt * 16 + 8 + rr) * 4 + w] = rs8[mt];
                }
            }
            __syncthreads();
            if (tid < 64) {
                float s = smf[SM_RED / 4 + tid * 4 + 0] + smf[SM_RED / 4 + tid * 4 + 1]
                        + smf[SM_RED / 4 + tid * 4 + 2] + smf[SM_RED / 4 + tid * 4 + 3];
                int j = jb + tid;
                out[rowi * N_ + j] = (mi + ment[b * N_ + j] + s + b3v) * (1.0f / 3.0f);
            }
        }
    }
}

// ---------------------------------------------------------------------------
extern "C" void kernel_launch(void* const* d_in, const int* in_sizes, int n_in,
                              void* d_out, int out_size)
{
    const float* g  = (const float*)d_in[0];
    const float* m  = (const float*)d_in[1];
    const float* W1 = (const float*)d_in[2];
    const float* b1 = (const float*)d_in[3];
    const float* W2 = (const float*)d_in[4];
    const float* b2 = (const float*)d_in[5];
    const float* W3 = (const float*)d_in[6];
    const float* b3 = (const float*)d_in[7];
    float* out = (float*)d_out;

    (void)cudaFuncSetAttribute(k_main,
                               cudaFuncAttributeMaxDynamicSharedMemorySize, SMEM_BYTES);

    k_precompute<<<64, 256>>>(g, W1, b1);
    k_prep_w1c<<<(8 * 160 * 64 + 255) / 256, 256>>>(W1);
    k_prep_w2t<<<(3 * 160 * 64 + 255) / 256, 256>>>(W2);
    k_main<<<B_ * N_, 128, SMEM_BYTES>>>(g, m, b2, W3, b3, out);
}

// round 8
// speedup vs baseline: 6.0191x; 1.1858x over previous
#include <cuda_runtime.h>
#include <cuda_bf16.h>
#include <cstdint>

// PairwiseScore via warp-level bf16 mma.sync, cp.async-pipelined.
// out[b,i,j] = (m_i + m_j + MLP3(g_i,g_j))/3,  B=2,N=256,E=512,H=150 (pad 160).
// One CTA per (b,i), 256 threads (8 warps), j-tiles of 128.
// Chunk stream per j-tile (k-chunks of 64): 8x W1c (GEMM1) + 3x W2^T (GEMM2),
// B tiles double-buffered via cp.async, one chunk ahead.

namespace {
constexpr int B_ = 2, N_ = 256, E_ = 512, H_ = 150;
constexpr int HS = 160;   // padded H
}

// ---- device scratch (no cudaMalloc allowed) ----
__device__ float g_HI[B_ * N_ * HS];
__device__ float g_HJ[B_ * N_ * HS];
// W1c^T bf16 pre-swizzled: 8 chunks x [160 n][64 k] (20480 B each)
__device__ __align__(16) unsigned char g_W1cT[8 * 20480];
// W2^T bf16 pre-swizzled: 3 chunks x [160 n][64 k]
__device__ __align__(16) unsigned char g_W2T[3 * 20480];

// swizzled byte offset inside a [rows][64] bf16 tile (128 B rows, 8x16B segs)
__device__ __forceinline__ int swz(int row, int k) {
    return row * 128 + (((k >> 3) ^ (row & 7)) * 16) + (k & 7) * 2;
}
__device__ __forceinline__ uint32_t smem_u32(const void* p) {
    uint32_t a;
    asm("{ .reg .u64 t; cvta.to.shared.u64 t, %1; cvt.u32.u64 %0, t; }" : "=r"(a) : "l"(p));
    return a;
}
#define CVT_BF2(res, lo, hi) asm("cvt.rn.bf16x2.f32 %0, %1, %2;" : "=r"(res) : "f"(hi), "f"(lo))

__device__ __forceinline__ void cp16(uint32_t dst, const void* src) {
    asm volatile("cp.async.cg.shared.global [%0], [%1], 16;" :: "r"(dst), "l"(src));
}
__device__ __forceinline__ void mma16816(float* d, const uint32_t* a, const uint32_t* bf) {
    asm volatile("mma.sync.aligned.m16n8k16.row.col.f32.bf16.bf16.f32 "
                 "{%0,%1,%2,%3}, {%4,%5,%6,%7}, {%8,%9}, {%0,%1,%2,%3};"
                 : "+f"(d[0]), "+f"(d[1]), "+f"(d[2]), "+f"(d[3])
                 : "r"(a[0]), "r"(a[1]), "r"(a[2]), "r"(a[3]), "r"(bf[0]), "r"(bf[1]));
}

// One 64-wide k-chunk. A tile [128][64] at aBase, B tile [160][64] at bBase.
// Warp (mh,ns): rows mh*64..+63, cols ns*40..+39 -> acc[4 mt][5 nt][4].
__device__ __forceinline__ void gemm_chunk(uint32_t aBase, uint32_t bBase,
                                           int mh, int ns, int lane, float (*acc)[5][4]) {
#pragma unroll
    for (int ks = 0; ks < 4; ks++) {
        uint32_t a[4][4];
#pragma unroll
        for (int mt = 0; mt < 4; mt++) {
            int row = mh * 64 + mt * 16 + ((lane >> 3) & 1) * 8 + (lane & 7);
            int seg = ks * 2 + (lane >> 4);
            uint32_t ad = aBase + row * 128 + ((seg ^ (row & 7)) * 16);
            asm volatile("ldmatrix.sync.aligned.m8n8.x4.shared.b16 {%0,%1,%2,%3}, [%4];"
                         : "=r"(a[mt][0]), "=r"(a[mt][1]), "=r"(a[mt][2]), "=r"(a[mt][3])
                         : "r"(ad));
        }
#pragma unroll
        for (int nt = 0; nt < 5; nt++) {
            int nrow = ns * 40 + nt * 8 + (lane & 7);
            int seg = ks * 2 + ((lane >> 3) & 1);
            uint32_t bd = bBase + nrow * 128 + ((seg ^ (nrow & 7)) * 16);
            uint32_t bf[2];
            asm volatile("ldmatrix.sync.aligned.m8n8.x2.shared.b16 {%0,%1}, [%2];"
                         : "=r"(bf[0]), "=r"(bf[1]) : "r"(bd));
#pragma unroll
            for (int mt = 0; mt < 4; mt++) mma16816(acc[mt][nt], a[mt], bf);
        }
    }
}

// smem byte map
constexpr int SM_GI  = 0;        // 512 f (2048 B)
constexpr int SM_HI  = 2048;     // 160 f
constexpr int SM_W3  = 2688;     // 160 f
constexpr int SM_B2  = 3328;     // 160 f
constexpr int SM_RED = 3968;     // 128*4 f (2048 B)
constexpr int SM_A1  = 6144;     // [128][64] bf16 swz (16384)
constexpr int SM_B0  = 22528;    // [160][64] bf16 swz (20480) x2 double buffer
constexpr int SM_A2  = 63488;    // 3 x [128][64] bf16 (49152)
constexpr int SMEM_BYTES = 112640;

// ---------------------------------------------------------------------------
// Merged prep kernel. Blocks 0..63: HI/HJ. 64..383: W1c. 384..503: W2^T.
// ---------------------------------------------------------------------------
__global__ void __launch_bounds__(256) k_prep(
    const float* __restrict__ g, const float* __restrict__ W1,
    const float* __restrict__ b1, const float* __restrict__ W2)
{
    const int bb = blockIdx.x;
    const int tid = threadIdx.x;
    if (bb >= 64) {
        if (bb < 384) {   // W1c^T -> bf16 swizzled chunks
            int idx = (bb - 64) * 256 + tid;
            int c = idx / (160 * 64), r = idx % (160 * 64);
            int n = r / 64, k = r % 64;
            float v = (n < H_) ? W1[(2 * E_ + c * 64 + k) * H_ + n] : 0.f;
            *(__nv_bfloat16*)(g_W1cT + c * 20480 + swz(n, k)) = __float2bfloat16(v);
        } else {          // W2^T -> bf16 swizzled chunks
            int idx = (bb - 384) * 256 + tid;
            int c = idx / (160 * 64), r = idx % (160 * 64);
            int n = r / 64, k = r % 64;
            int kk = c * 64 + k;
            float v = (n < H_ && kk < H_) ? W2[kk * H_ + n] : 0.f;
            *(__nv_bfloat16*)(g_W2T + c * 20480 + swz(n, k)) = __float2bfloat16(v);
        }
        return;
    }
    // HI/HJ precompute: 8 rows per block
    __shared__ float sm[8 * 33 + 2 * 32 * 152 + 64];
    float* gs = sm;
    float* wa = sm + 8 * 33;
    float* wb = wa + 32 * 152;
    const int tx = tid & 31, ty = tid >> 5;
    const int r0 = bb * 8;
    float acca[5] = {0, 0, 0, 0, 0}, accb[5] = {0, 0, 0, 0, 0};
    for (int ec = 0; ec < E_; ec += 32) {
        __syncthreads();
        { int jj = tid >> 5, ee = tid & 31; gs[jj * 33 + ee] = g[(r0 + jj) * E_ + ec + ee]; }
        for (int q = tid; q < 32 * H_; q += 256) {
            int r = q / H_, c = q % H_;
            wa[r * 152 + c] = W1[(ec + r) * H_ + c];
            wb[r * 152 + c] = W1[(E_ + ec + r) * H_ + c];
        }
        __syncthreads();
#pragma unroll 8
        for (int e = 0; e < 32; e++) {
            float a = gs[ty * 33 + e];
#pragma unroll
            for (int k = 0; k < 5; k++) {
                acca[k] += a * wa[e * 152 + tx + 32 * k];
                accb[k] += a * wb[e * 152 + tx + 32 * k];
            }
        }
    }
    const int row = r0 + ty;
#pragma unroll
    for (int k = 0; k < 5; k++) {
        int h = tx + 32 * k;
        bool v = (h < H_);
        g_HI[row * HS + h] = v ? (acca[k] + b1[h]) : 0.f;
        g_HJ[row * HS + h] = v ? accb[k] : 0.f;
    }
}

// ---------------------------------------------------------------------------
// Main kernel: one CTA per (b,i), 256 threads (8 warps), 2 CTAs/SM.
// ---------------------------------------------------------------------------
__global__ void __launch_bounds__(256, 2) k_main(
    const float* __restrict__ g, const float* __restrict__ ment,
    const float* __restrict__ b2, const float* __restrict__ W3,
    const float* __restrict__ b3, float* __restrict__ out)
{
    extern __shared__ char smc[];
    float* smf = (float*)smc;
    const uint32_t sb = smem_u32(smc);
    const int tid = threadIdx.x, w = tid >> 5, lane = tid & 31;
    const int mh = w & 1, ns = w >> 1;
    const int b = blockIdx.x >> 8;
    const int rowi = blockIdx.x;

    // prefetch chunk 0 (W1c c0) into B buffer 0
    for (int q = tid; q < 1280; q += 256)
        cp16(sb + SM_B0 + q * 16, (const char*)g_W1cT + q * 16);
    asm volatile("cp.async.commit_group;");

    for (int q = tid; q < E_; q += 256) smf[SM_GI / 4 + q] = g[rowi * E_ + q];
    for (int q = tid; q < HS; q += 256) {
        smf[SM_HI / 4 + q] = g_HI[rowi * HS + q];   // already zero-padded
        smf[SM_W3 / 4 + q] = (q < H_) ? W3[q] : 0.f;
        smf[SM_B2 / 4 + q] = (q < H_) ? b2[q] : 0.f;
    }
    {   // zero A2 chunk 2 (k 160..191 region stays zero forever)
        uint4 z = make_uint4(0, 0, 0, 0);
        for (int q = tid; q < 1024; q += 256)
            ((uint4*)(smc + SM_A2 + 2 * 16384))[q] = z;
    }

    const float mi = ment[rowi];
    const float b3v = b3[0];
    float acc[4][5][4];   // shared between GEMM1 and GEMM2 (reset at u==0/u==8)

    for (int t = 0; t < 22; t++) {
        const int u = (t >= 11) ? t - 11 : t;        // chunk id in j-tile stream
        const int jb = (t >= 11) ? 128 : 0;

        __syncthreads();   // all warps done with previous gemm / A1 / RED

        // prefetch chunk t+1 into alternate buffer (always commit a group)
        if (t + 1 < 22) {
            int t2 = t + 1;
            int u2 = (t2 >= 11) ? t2 - 11 : t2;
            const char* src = (u2 < 8) ? (const char*)g_W1cT + u2 * 20480
                                       : (const char*)g_W2T + (u2 - 8) * 20480;
            uint32_t dstb = sb + SM_B0 + ((t2 & 1) ? 20480u : 0u);
            for (int q = tid; q < 1280; q += 256)
                cp16(dstb + q * 16, src + q * 16);
        }
        asm volatile("cp.async.commit_group;");

        if (u == 0) {
#pragma unroll
            for (int mt = 0; mt < 4; mt++)
#pragma unroll
                for (int nt = 0; nt < 5; nt++)
#pragma unroll
                    for (int q = 0; q < 4; q++) acc[mt][nt][q] = 0.f;
        }

        if (u < 8) {
            // A-fill: A1 = bf16(g_j * g_i) for this k-chunk, rows jb..jb+127
#pragma unroll
            for (int s4 = 0; s4 < 4; s4++) {
                int s = s4 * 256 + tid;          // 0..1023
                int row = s >> 3, seg = s & 7;
                const float4* gp = (const float4*)(g + (b * N_ + jb + row) * E_ + u * 64 + seg * 8);
                float4 ga = gp[0], gb_ = gp[1];
                const float4* ip = (const float4*)(smf + SM_GI / 4 + u * 64 + seg * 8);
                float4 ia = ip[0], ib = ip[1];
                uint32_t p0, p1, p2, p3;
                CVT_BF2(p0, ga.x * ia.x, ga.y * ia.y);
                CVT_BF2(p1, ga.z * ia.z, ga.w * ia.w);
                CVT_BF2(p2, gb_.x * ib.x, gb_.y * ib.y);
                CVT_BF2(p3, gb_.z * ib.z, gb_.w * ib.w);
                *(uint4*)(smc + SM_A1 + row * 128 + ((seg ^ (row & 7)) * 16)) =
                    make_uint4(p0, p1, p2, p3);
            }
        } else if (u == 8) {
            // epilogue 1: A2 = bf16(relu(acc + HI + HJ)); then reset acc
            const float* hjb = g_HJ + (b * N_ + jb) * HS;
#pragma unroll
            for (int mt = 0; mt < 4; mt++) {
                int r0 = mh * 64 + mt * 16 + (lane >> 2);
#pragma unroll
                for (int nt = 0; nt < 5; nt++) {
                    int h = ns * 40 + nt * 8 + (lane & 3) * 2;
                    float2 hi2 = *(const float2*)(smf + SM_HI / 4 + h);
                    float2 hj0 = *(const float2*)(hjb + r0 * HS + h);
                    float2 hj8 = *(const float2*)(hjb + (r0 + 8) * HS + h);
                    float v0 = fmaxf(acc[mt][nt][0] + hi2.x + hj0.x, 0.f);
                    float v1 = fmaxf(acc[mt][nt][1] + hi2.y + hj0.y, 0.f);
                    float v2 = fmaxf(acc[mt][nt][2] + hi2.x + hj8.x, 0.f);
                    float v3 = fmaxf(acc[mt][nt][3] + hi2.y + hj8.y, 0.f);
                    int base = SM_A2 + (h >> 6) * 16384;
                    int kk = h & 63;
                    uint32_t pk;
                    CVT_BF2(pk, v0, v1);
                    *(uint32_t*)(smc + base + swz(r0, kk)) = pk;
                    CVT_BF2(pk, v2, v3);
                    *(uint32_t*)(smc + base + swz(r0 + 8, kk)) = pk;
                    acc[mt][nt][0] = acc[mt][nt][1] = acc[mt][nt][2] = acc[mt][nt][3] = 0.f;
                }
            }
        }

        asm volatile("cp.async.wait_group 1;");   // chunk t's B has landed
        __syncthreads();                          // A1/A2 writes + B visible

        uint32_t curB = sb + SM_B0 + ((t & 1) ? 20480u : 0u);
        uint32_t aB = (u < 8) ? (sb + SM_A1) : (sb + SM_A2 + (u - 8) * 16384);
        gemm_chunk(aB, curB, mh, ns, lane, acc);

        if (u == 10) {
            // epilogue 2: relu(acc + b2) . w3, cross-warp reduce, write out
            float rs0[4], rs8[4];
#pragma unroll
            for (int mt = 0; mt < 4; mt++) {
                float s0 = 0.f, s8 = 0.f;
#pragma unroll
                for (int nt = 0; nt < 5; nt++) {
                    int h = ns * 40 + nt * 8 + (lane & 3) * 2;
                    float w30 = smf[SM_W3 / 4 + h], w31 = smf[SM_W3 / 4 + h + 1];
                    float bb0 = smf[SM_B2 / 4 + h], bb1 = smf[SM_B2 / 4 + h + 1];
                    s0 += fmaxf(acc[mt][nt][0] + bb0, 0.f) * w30
                        + fmaxf(acc[mt][nt][1] + bb1, 0.f) * w31;
                    s8 += fmaxf(acc[mt][nt][2] + bb0, 0.f) * w30
                        + fmaxf(acc[mt][nt][3] + bb1, 0.f) * w31;
                }
                s0 += __shfl_xor_sync(0xffffffffu, s0, 1);
                s0 += __shfl_xor_sync(0xffffffffu, s0, 2);
                s8 += __shfl_xor_sync(0xffffffffu, s8, 1);
                s8 += __shfl_xor_sync(0xffffffffu, s8, 2);
                rs0[mt] = s0; rs8[mt] = s8;
            }
            if ((lane & 3) == 0) {
                int rr = lane >> 2;
#pragma unroll
                for (int mt = 0; mt < 4; mt++) {
                    smf[SM_RED / 4 + (mh * 64 + mt * 16 + rr) * 4 + ns] = rs0[mt];
                    smf[SM_RED / 4 + (mh * 64 + mt * 16 + 8 + rr) * 4 + ns] = rs8[mt];
                }
            }
            __syncthreads();
            if (tid < 128) {
                float s = smf[SM_RED / 4 + tid * 4 + 0] + smf[SM_RED / 4 + tid * 4 + 1]
                        + smf[SM_RED / 4 + tid * 4 + 2] + smf[SM_RED / 4 + tid * 4 + 3];
                int j = jb + tid;
                out[rowi * N_ + j] = (mi + ment[b * N_ + j] + s + b3v) * (1.0f / 3.0f);
            }
        }
    }
}

// ---------------------------------------------------------------------------
extern "C" void kernel_launch(void* const* d_in, const int* in_sizes, int n_in,
                              void* d_out, int out_size)
{
    const float* g  = (const float*)d_in[0];
    const float* m  = (const float*)d_in[1];
    const float* W1 = (const float*)d_in[2];
    const float* b1 = (const float*)d_in[3];
    const float* W2 = (const float*)d_in[4];
    const float* b2 = (const float*)d_in[5];
    const float* W3 = (const float*)d_in[6];
    const float* b3 = (const float*)d_in[7];
    float* out = (float*)d_out;

    (void)cudaFuncSetAttribute(k_main,
                               cudaFuncAttributeMaxDynamicSharedMemorySize, SMEM_BYTES);

    k_prep<<<504, 256>>>(g, W1, b1, W2);
    k_main<<<B_ * N_, 256, SMEM_BYTES>>>(g, m, b2, W3, b3, out);
}

// round 9
// speedup vs baseline: 8.2042x; 1.3630x over previous
#include <cuda_runtime.h>
#include <cuda_bf16.h>
#include <cstdint>

// PairwiseScore via warp-level bf16 mma.sync, cp.async-pipelined.
// out[b,i,j] = (m_i + m_j + MLP3(g_i,g_j))/3,  B=2,N=256,E=512,H=150 (pad 160).
// One CTA per (b,i), 256 threads (8 warps), j-tiles of 128.
// A operand pre-converted to bf16 and pre-swizzled in gmem (g_sw); A-fill is a
// linear LDG/STS pass with bf16x2 multiply by gi. B tiles double-buffered cp.async.

namespace {
constexpr int B_ = 2, N_ = 256, E_ = 512, H_ = 150;
constexpr int HS = 160;   // padded H
}

// ---- device scratch (no cudaMalloc allowed) ----
__device__ float g_HI[B_ * N_ * HS];
__device__ float g_HJ[B_ * N_ * HS];
// W1c^T bf16 pre-swizzled: 8 chunks x [160 n][64 k] (20480 B each)
__device__ __align__(16) unsigned char g_W1cT[8 * 20480];
// W2^T bf16 pre-swizzled: 3 chunks x [160 n][64 k]
__device__ __align__(16) unsigned char g_W2T[3 * 20480];
// g bf16 pre-swizzled A-tiles: 32 tiles [(b*2+jt)*8+u] x [128 r][8 seg'] x 16B
__device__ __align__(16) unsigned char g_sw[32 * 16384];

// swizzled byte offset inside a [rows][64] bf16 tile (128 B rows, 8x16B segs)
__device__ __forceinline__ int swz(int row, int k) {
    return row * 128 + (((k >> 3) ^ (row & 7)) * 16) + (k & 7) * 2;
}
__device__ __forceinline__ uint32_t smem_u32(const void* p) {
    uint32_t a;
    asm("{ .reg .u64 t; cvta.to.shared.u64 t, %1; cvt.u32.u64 %0, t; }" : "=r"(a) : "l"(p));
    return a;
}
#define CVT_BF2(res, lo, hi) asm("cvt.rn.bf16x2.f32 %0, %1, %2;" : "=r"(res) : "f"(hi), "f"(lo))
#define MULB2(res, a, b) asm("mul.bf16x2 %0, %1, %2;" : "=r"(res) : "r"(a), "r"(b))

__device__ __forceinline__ void cp16(uint32_t dst, const void* src) {
    asm volatile("cp.async.cg.shared.global [%0], [%1], 16;" :: "r"(dst), "l"(src));
}
__device__ __forceinline__ void mma16816(float* d, const uint32_t* a, const uint32_t* bf) {
    asm volatile("mma.sync.aligned.m16n8k16.row.col.f32.bf16.bf16.f32 "
                 "{%0,%1,%2,%3}, {%4,%5,%6,%7}, {%8,%9}, {%0,%1,%2,%3};"
                 : "+f"(d[0]), "+f"(d[1]), "+f"(d[2]), "+f"(d[3])
                 : "r"(a[0]), "r"(a[1]), "r"(a[2]), "r"(a[3]), "r"(bf[0]), "r"(bf[1]));
}

// One 64-wide k-chunk. A tile [128][64] at aBase, B tile [160][64] at bBase.
// Warp (mh,ns): rows mh*64..+63, cols ns*40..+39 -> acc[4 mt][5 nt][4].
__device__ __forceinline__ void gemm_chunk(uint32_t aBase, uint32_t bBase,
                                           int mh, int ns, int lane, float (*acc)[5][4]) {
#pragma unroll
    for (int ks = 0; ks < 4; ks++) {
        uint32_t a[4][4];
#pragma unroll
        for (int mt = 0; mt < 4; mt++) {
            int row = mh * 64 + mt * 16 + ((lane >> 3) & 1) * 8 + (lane & 7);
            int seg = ks * 2 + (lane >> 4);
            uint32_t ad = aBase + row * 128 + ((seg ^ (row & 7)) * 16);
            asm volatile("ldmatrix.sync.aligned.m8n8.x4.shared.b16 {%0,%1,%2,%3}, [%4];"
                         : "=r"(a[mt][0]), "=r"(a[mt][1]), "=r"(a[mt][2]), "=r"(a[mt][3])
                         : "r"(ad));
        }
        uint32_t bfr[5][2];
#pragma unroll
        for (int ntp = 0; ntp < 2; ntp++) {     // nt pairs (0,1),(2,3) via x4
            int grp = lane >> 3;
            int ntv = ntp * 2 + (grp >> 1);
            int seg = ks * 2 + (grp & 1);
            int nrow = ns * 40 + ntv * 8 + (lane & 7);
            uint32_t bd = bBase + nrow * 128 + ((seg ^ (nrow & 7)) * 16);
            asm volatile("ldmatrix.sync.aligned.m8n8.x4.shared.b16 {%0,%1,%2,%3}, [%4];"
                         : "=r"(bfr[ntp * 2][0]), "=r"(bfr[ntp * 2][1]),
                           "=r"(bfr[ntp * 2 + 1][0]), "=r"(bfr[ntp * 2 + 1][1])
                         : "r"(bd));
        }
        {                                        // nt = 4 via x2
            int nrow = ns * 40 + 32 + (lane & 7);
            int seg = ks * 2 + ((lane >> 3) & 1);
            uint32_t bd = bBase + nrow * 128 + ((seg ^ (nrow & 7)) * 16);
            asm volatile("ldmatrix.sync.aligned.m8n8.x2.shared.b16 {%0,%1}, [%2];"
                         : "=r"(bfr[4][0]), "=r"(bfr[4][1]) : "r"(bd));
        }
#pragma unroll
        for (int nt = 0; nt < 5; nt++)
#pragma unroll
            for (int mt = 0; mt < 4; mt++) mma16816(acc[mt][nt], a[mt], bfr[nt]);
    }
}

// smem byte map
constexpr int SM_HI  = 0;        // 160 f (640 B)
constexpr int SM_W3  = 640;      // 160 f
constexpr int SM_B2  = 1280;     // 160 f
constexpr int SM_GIB = 1920;     // 512 bf16 (1024 B)
constexpr int SM_RED = 2944;     // 128*4 f (2048 B)
constexpr int SM_A1  = 5120;     // [128][64] bf16 swz (16384)
constexpr int SM_B0  = 21504;    // [160][64] bf16 swz (20480) x2 double buffer
constexpr int SM_A2  = 62464;    // 3 x [128][64] bf16 (49152)
constexpr int SMEM_BYTES = 111616;

// ---------------------------------------------------------------------------
// Merged prep kernel.
// bb 0..127   : HI/HJ (4 rows each)
// bb 128..447 : W1c^T bf16 swizzled
// bb 448..567 : W2^T bf16 swizzled
// bb 568..695 : g -> g_sw bf16 pre-swizzled A tiles
// ---------------------------------------------------------------------------
__global__ void __launch_bounds__(256) k_prep(
    const float* __restrict__ g, const float* __restrict__ W1,
    const float* __restrict__ b1, const float* __restrict__ W2)
{
    const int bb = blockIdx.x;
    const int tid = threadIdx.x;
    if (bb >= 128) {
        if (bb < 448) {           // W1c^T (n-fastest: coalesced LDG)
            int idx = (bb - 128) * 256 + tid;           // 8*64*160 = 81920
            int c = idx / 10240, r = idx % 10240;
            int kk = r / 160, n = r % 160;
            float v = (n < H_) ? W1[(2 * E_ + c * 64 + kk) * H_ + n] : 0.f;
            *(__nv_bfloat16*)(g_W1cT + c * 20480 + swz(n, kk)) = __float2bfloat16(v);
        } else if (bb < 568) {    // W2^T
            int idx = (bb - 448) * 256 + tid;           // 3*64*160 = 30720
            int c = idx / 10240, r = idx % 10240;
            int kk = r / 160, n = r % 160;
            int kg = c * 64 + kk;
            float v = (n < H_ && kg < H_) ? W2[kg * H_ + n] : 0.f;
            *(__nv_bfloat16*)(g_W2T + c * 20480 + swz(n, kk)) = __float2bfloat16(v);
        } else {                  // g_sw
            int slot = (bb - 568) * 256 + tid;          // 32768 16B slots
            int tile = slot >> 10, q = slot & 1023;
            int r = q >> 3, sp = q & 7;
            int b = tile >> 4, jt = (tile >> 3) & 1, u = tile & 7;
            int grow = b * 256 + jt * 128 + r;
            int e0 = u * 64 + ((sp ^ (r & 7)) * 8);
            const float4* src = (const float4*)(g + grow * E_ + e0);
            float4 v0 = src[0], v1 = src[1];
            uint4 o;
            CVT_BF2(o.x, v0.x, v0.y);
            CVT_BF2(o.y, v0.z, v0.w);
            CVT_BF2(o.z, v1.x, v1.y);
            CVT_BF2(o.w, v1.z, v1.w);
            *(uint4*)(g_sw + slot * 16) = o;
        }
        return;
    }
    // HI/HJ: 4 rows per block, thread (ty = row, tx = h mod 64)
    __shared__ float sm[4 * 33 + 2 * 32 * 152 + 32];
    float* gs = sm;
    float* wa = sm + 4 * 33;
    float* wb = wa + 32 * 152;
    const int tx = tid & 63, ty = tid >> 6;
    const int r0 = bb * 4;
    const bool v2 = (tx < 22);    // h = tx+128 < 150
    float aA[3] = {0, 0, 0}, aB[3] = {0, 0, 0};
    for (int ec = 0; ec < E_; ec += 32) {
        __syncthreads();
        if (tid < 128) {
            int jj = tid >> 5, ee = tid & 31;
            gs[jj * 33 + ee] = g[(r0 + jj) * E_ + ec + ee];
        }
        for (int q = tid; q < 32 * H_; q += 256) {
            int r = q / H_, c = q % H_;
            wa[r * 152 + c] = W1[(ec + r) * H_ + c];
            wb[r * 152 + c] = W1[(E_ + ec + r) * H_ + c];
        }
        __syncthreads();
#pragma unroll 8
        for (int e = 0; e < 32; e++) {
            float a = gs[ty * 33 + e];
            aA[0] += a * wa[e * 152 + tx];
            aA[1] += a * wa[e * 152 + tx + 64];
            if (v2) aA[2] += a * wa[e * 152 + tx + 128];
            aB[0] += a * wb[e * 152 + tx];
            aB[1] += a * wb[e * 152 + tx + 64];
            if (v2) aB[2] += a * wb[e * 152 + tx + 128];
        }
    }
    const int row = r0 + ty;
    g_HI[row * HS + tx] = aA[0] + b1[tx];
    g_HJ[row * HS + tx] = aB[0];
    g_HI[row * HS + tx + 64] = aA[1] + b1[tx + 64];
    g_HJ[row * HS + tx + 64] = aB[1];
    if (tx < 32) {
        int h2 = tx + 128;
        g_HI[row * HS + h2] = (h2 < H_) ? (aA[2] + b1[h2]) : 0.f;
        g_HJ[row * HS + h2] = (h2 < H_) ? aB[2] : 0.f;
    }
}

// ---------------------------------------------------------------------------
// Main kernel: one CTA per (b,i), 256 threads (8 warps), 2 CTAs/SM.
// ---------------------------------------------------------------------------
__global__ void __launch_bounds__(256, 2) k_main(
    const float* __restrict__ g, const float* __restrict__ ment,
    const float* __restrict__ b2, const float* __restrict__ W3,
    const float* __restrict__ b3, float* __restrict__ out)
{
    extern __shared__ char smc[];
    float* smf = (float*)smc;
    const uint32_t sb = smem_u32(smc);
    const int tid = threadIdx.x, w = tid >> 5, lane = tid & 31;
    const int mh = w & 1, ns = w >> 1;
    const int b = blockIdx.x >> 8;
    const int rowi = blockIdx.x;

    // prefetch chunk 0 (W1c c0) into B buffer 0
    for (int q = tid; q < 1280; q += 256)
        cp16(sb + SM_B0 + q * 16, (const char*)g_W1cT + q * 16);
    asm volatile("cp.async.commit_group;");

    {   // gi -> bf16 in smem
        float2 v = *(const float2*)(g + rowi * E_ + tid * 2);
        uint32_t pk;
        CVT_BF2(pk, v.x, v.y);
        *(uint32_t*)(smc + SM_GIB + tid * 4) = pk;
    }
    for (int q = tid; q < HS; q += 256) {
        smf[SM_HI / 4 + q] = g_HI[rowi * HS + q];   // already zero-padded
        smf[SM_W3 / 4 + q] = (q < H_) ? W3[q] : 0.f;
        smf[SM_B2 / 4 + q] = (q < H_) ? b2[q] : 0.f;
    }
    {   // zero A2 chunk 2 (k 160..191 region stays zero forever)
        uint4 z = make_uint4(0, 0, 0, 0);
        for (int q = tid; q < 1024; q += 256)
            ((uint4*)(smc + SM_A2 + 2 * 16384))[q] = z;
    }

    const float mi = ment[rowi];
    const float b3v = b3[0];
    float acc[4][5][4];   // shared between GEMM1 and GEMM2 (reset at u==0/u==8)

    for (int t = 0; t < 22; t++) {
        const int u = (t >= 11) ? t - 11 : t;        // chunk id in j-tile stream
        const int jt = (t >= 11) ? 1 : 0;
        const int jb = jt * 128;

        __syncthreads();   // all warps done with previous gemm / A1 / RED

        // prefetch chunk t+1 into alternate buffer (always commit a group)
        if (t + 1 < 22) {
            int t2 = t + 1;
            int u2 = (t2 >= 11) ? t2 - 11 : t2;
            const char* src = (u2 < 8) ? (const char*)g_W1cT + u2 * 20480
                                       : (const char*)g_W2T + (u2 - 8) * 20480;
            uint32_t dstb = sb + SM_B0 + ((t2 & 1) ? 20480u : 0u);
            for (int q = tid; q < 1280; q += 256)
                cp16(dstb + q * 16, src + q * 16);
        }
        asm volatile("cp.async.commit_group;");

        if (u == 0) {
#pragma unroll
            for (int mt = 0; mt < 4; mt++)
#pragma unroll
                for (int nt = 0; nt < 5; nt++)
#pragma unroll
                    for (int q = 0; q < 4; q++) acc[mt][nt][q] = 0.f;
        }

        if (u < 8) {
            // A-fill: A1 = bf16(g_j) * bf16(g_i), linear copy from pre-swizzled g_sw
            const char* gsrc = (const char*)g_sw + ((b * 2 + jt) * 8 + u) * 16384;
#pragma unroll
            for (int s4 = 0; s4 < 4; s4++) {
                int slot = s4 * 256 + tid;           // 0..1023
                uint4 gv = *(const uint4*)(gsrc + slot * 16);
                int r = slot >> 3, sp = slot & 7;
                uint4 iv = *(const uint4*)(smc + SM_GIB + u * 128 + ((sp ^ (r & 7)) * 16));
                uint4 o;
                MULB2(o.x, gv.x, iv.x);
                MULB2(o.y, gv.y, iv.y);
                MULB2(o.z, gv.z, iv.z);
                MULB2(o.w, gv.w, iv.w);
                *(uint4*)(smc + SM_A1 + slot * 16) = o;
            }
        } else if (u == 8) {
            // epilogue 1: A2 = bf16(relu(acc + HI + HJ)); then reset acc
            const float* hjb = g_HJ + (b * N_ + jb) * HS;
#pragma unroll
            for (int mt = 0; mt < 4; mt++) {
                int r0 = mh * 64 + mt * 16 + (lane >> 2);
#pragma unroll
                for (int nt = 0; nt < 5; nt++) {
                    int h = ns * 40 + nt * 8 + (lane & 3) * 2;
                    float2 hi2 = *(const float2*)(smf + SM_HI / 4 + h);
                    float2 hj0 = *(const float2*)(hjb + r0 * HS + h);
                    float2 hj8 = *(const float2*)(hjb + (r0 + 8) * HS + h);
                    float v0 = fmaxf(acc[mt][nt][0] + hi2.x + hj0.x, 0.f);
                    float v1 = fmaxf(acc[mt][nt][1] + hi2.y + hj0.y, 0.f);
                    float v2 = fmaxf(acc[mt][nt][2] + hi2.x + hj8.x, 0.f);
                    float v3 = fmaxf(acc[mt][nt][3] + hi2.y + hj8.y, 0.f);
                    int base = SM_A2 + (h >> 6) * 16384;
                    int kk = h & 63;
                    uint32_t pk;
                    CVT_BF2(pk, v0, v1);
                    *(uint32_t*)(smc + base + swz(r0, kk)) = pk;
                    CVT_BF2(pk, v2, v3);
                    *(uint32_t*)(smc + base + swz(r0 + 8, kk)) = pk;
                    acc[mt][nt][0] = acc[mt][nt][1] = acc[mt][nt][2] = acc[mt][nt][3] = 0.f;
                }
            }
        }

        asm volatile("cp.async.wait_group 1;");   // chunk t's B has landed
        __syncthreads();                          // A1/A2 writes + B visible

        uint32_t curB = sb + SM_B0 + ((t & 1) ? 20480u : 0u);
        uint32_t aB = (u < 8) ? (sb + SM_A1) : (sb + SM_A2 + (u - 8) * 16384);
        gemm_chunk(aB, curB, mh, ns, lane, acc);

        if (u == 10) {
            // epilogue 2: relu(acc + b2) . w3, cross-warp reduce, write out
            float rs0[4], rs8[4];
#pragma unroll
            for (int mt = 0; mt < 4; mt++) {
                float s0 = 0.f, s8 = 0.f;
#pragma unroll
                for (int nt = 0; nt < 5; nt++) {
                    int h = ns * 40 + nt * 8 + (lane & 3) * 2;
                    float w30 = smf[SM_W3 / 4 + h], w31 = smf[SM_W3 / 4 + h + 1];
                    float bb0 = smf[SM_B2 / 4 + h], bb1 = smf[SM_B2 / 4 + h + 1];
                    s0 += fmaxf(acc[mt][nt][0] + bb0, 0.f) * w30
                        + fmaxf(acc[mt][nt][1] + bb1, 0.f) * w31;
                    s8 += fmaxf(acc[mt][nt][2] + bb0, 0.f) * w30
                        + fmaxf(acc[mt][nt][3] + bb1, 0.f) * w31;
                }
                s0 += __shfl_xor_sync(0xffffffffu, s0, 1);
                s0 += __shfl_xor_sync(0xffffffffu, s0, 2);
                s8 += __shfl_xor_sync(0xffffffffu, s8, 1);
                s8 += __shfl_xor_sync(0xffffffffu, s8, 2);
                rs0[mt] = s0; rs8[mt] = s8;
            }
            if ((lane & 3) == 0) {
                int rr = lane >> 2;
#pragma unroll
                for (int mt = 0; mt < 4; mt++) {
                    smf[SM_RED / 4 + (mh * 64 + mt * 16 + rr) * 4 + ns] = rs0[mt];
                    smf[SM_RED / 4 + (mh * 64 + mt * 16 + 8 + rr) * 4 + ns] = rs8[mt];
                }
            }
            __syncthreads();
            if (tid < 128) {
                float s = smf[SM_RED / 4 + tid * 4 + 0] + smf[SM_RED / 4 + tid * 4 + 1]
                        + smf[SM_RED / 4 + tid * 4 + 2] + smf[SM_RED / 4 + tid * 4 + 3];
                int j = jb + tid;
                out[rowi * N_ + j] = (mi + ment[b * N_ + j] + s + b3v) * (1.0f / 3.0f);
            }
        }
    }
}

// ---------------------------------------------------------------------------
extern "C" void kernel_launch(void* const* d_in, const int* in_sizes, int n_in,
                              void* d_out, int out_size)
{
    const float* g  = (const float*)d_in[0];
    const float* m  = (const float*)d_in[1];
    const float* W1 = (const float*)d_in[2];
    const float* b1 = (const float*)d_in[3];
    const float* W2 = (const float*)d_in[4];
    const float* b2 = (const float*)d_in[5];
    const float* W3 = (const float*)d_in[6];
    const float* b3 = (const float*)d_in[7];
    float* out = (float*)d_out;

    (void)cudaFuncSetAttribute(k_main,
                               cudaFuncAttributeMaxDynamicSharedMemorySize, SMEM_BYTES);

    k_prep<<<696, 256>>>(g, W1, b1, W2);
    k_main<<<B_ * N_, 256, SMEM_BYTES>>>(g, m, b2, W3, b3, out);
}